// round 16
// baseline (speedup 1.0000x reference)
#include <cuda_runtime.h>
#include <stdint.h>

// ---------------------------------------------------------------------------
// octree_level, int32-key-overflow semantics (verified rel=0 in R13/R14).
// R16 = R15 + fix: cached key is the QUERY (aliased, valid-zone) parent index,
// and scatter restores the presence check. 6 launches.
// ---------------------------------------------------------------------------

#define PB_WORDS    (1u << 21)                 // 2^26 bits / 32  (8 MB)
#define CHUNK_WORDS 1024u
#define NCHUNKS     (PB_WORDS / CHUNK_WORDS)   // 2048
#define NMAX        2200000

__device__ __align__(16) unsigned g_pbm[PB_WORDS];
__device__ unsigned short g_woff16[PB_WORDS];
__device__ unsigned g_partial[NCHUNKS];
__device__ unsigned g_chunkoff[NCHUNKS];
__device__ unsigned g_key[NMAX];                         // (query_idx<<3)|slot
__device__ __align__(16) unsigned g_cmask[NMAX / 4 + 2];

// F: zero bitmap + chunk counters + cmask; parent zone = -1
__global__ void k_fill(float* __restrict__ outP, long long n3, int cmw) {
    long long i = (long long)blockIdx.x * blockDim.x + threadIdx.x;
    if (i < PB_WORDS / 4) ((uint4*)g_pbm)[i] = make_uint4(0u, 0u, 0u, 0u);
    if (i < NCHUNKS) g_partial[i] = 0u;
    if (i * 4 < cmw) {
        long long w = i * 4;
        if (w + 3 < cmw) ((uint4*)g_cmask)[i] = make_uint4(0u, 0u, 0u, 0u);
        else for (long long k = w; k < cmw; k++) g_cmask[k] = 0u;
    }
    long long e = i * 4;
    if (e + 3 < n3) {
        ((float4*)outP)[i] = make_float4(-1.f, -1.f, -1.f, -1.f);
    } else if (e < n3) {
        for (long long k = e; k < n3; k++) outP[k] = -1.0f;
    }
}

// K1: mark own-parent bit (wrapped key order); cache the QUERY key
__global__ void k_mark(const float* __restrict__ leaf, int n) {
    int i = blockIdx.x * blockDim.x + threadIdx.x;
    if (i >= n) return;
    int x = (int)leaf[3 * i + 0];
    int y = (int)leaf[3 * i + 1];
    int z = (int)leaf[3 * i + 2];
    x = min(max(x, 0), 1023); y = min(max(y, 0), 1023); z = min(max(z, 0), 1023);
    unsigned yz = ((unsigned)(y >> 1) << 9) | (unsigned)(z >> 1);
    // own parent (mod-256 wrapped, signed order via ^128) -> presence bit
    unsigned tm = (((unsigned)(x >> 1)) & 255u) ^ 128u;
    unsigned midx = (tm << 18) | yz;
    // aliased query parent ((x mod 256)>>1, always valid zone) -> occupancy
    unsigned tq = (((unsigned)x & 255u) >> 1) + 128u;
    unsigned qidx = (tq << 18) | yz;
    unsigned c = ((unsigned)(x & 1) << 2) | ((unsigned)(y & 1) << 1) | (unsigned)(z & 1);
    g_key[i] = (qidx << 3) | c;
    unsigned bit = 1u << (midx & 31u);
    unsigned old = atomicOr(&g_pbm[midx >> 5], bit);
    if (!(old & bit)) atomicAdd(&g_partial[midx >> 15], 1u);  // fused count
}

// P2: shuffle-based exclusive scan of 2048 chunk counts
__global__ void k_scan() {
    __shared__ unsigned wsum[32];
    unsigned t = threadIdx.x, lane = t & 31u, wid = t >> 5;
    unsigned v0 = g_partial[2 * t + 0], v1 = g_partial[2 * t + 1];
    unsigned s = v0 + v1;
    unsigned x = s;
#pragma unroll
    for (int o = 1; o < 32; o <<= 1) {
        unsigned y = __shfl_up_sync(0xffffffffu, x, o);
        if (lane >= (unsigned)o) x += y;
    }
    if (lane == 31u) wsum[wid] = x;
    __syncthreads();
    if (wid == 0) {
        unsigned w = wsum[lane];
#pragma unroll
        for (int o = 1; o < 32; o <<= 1) {
            unsigned y = __shfl_up_sync(0xffffffffu, w, o);
            if (lane >= (unsigned)o) w += y;
        }
        wsum[lane] = w;
    }
    __syncthreads();
    unsigned base = ((wid > 0u) ? wsum[wid - 1] : 0u) + x - s;
    g_chunkoff[2 * t + 0] = base;
    g_chunkoff[2 * t + 1] = base + v0;
}

// P3a: u16 chunk-relative word offsets + valid parent rows (wrapped keep -1)
__global__ void k_emit(float* __restrict__ outP, int n) {
    __shared__ unsigned sh[256];
    unsigned b = blockIdx.x, t = threadIdx.x;
    unsigned w0 = b * CHUNK_WORDS + t * 4u;
    const uint4* base = ((const uint4*)g_pbm) + b * (CHUNK_WORDS / 4);
    uint4 w = base[t];
    unsigned words[4] = { w.x, w.y, w.z, w.w };
    unsigned s = __popc(w.x) + __popc(w.y) + __popc(w.z) + __popc(w.w);
    sh[t] = s; __syncthreads();
    for (int o = 1; o < 256; o <<= 1) {
        unsigned add = (t >= (unsigned)o) ? sh[t - o] : 0u;
        __syncthreads();
        sh[t] += add;
        __syncthreads();
    }
    unsigned rel = sh[t] - s;
    unsigned chunkbase = g_chunkoff[b];
#pragma unroll
    for (int j = 0; j < 4; j++) {
        unsigned wi = w0 + (unsigned)j;
        g_woff16[wi] = (unsigned short)rel;
        unsigned m = words[j];
        while (m) {
            int bit = __ffs((int)m) - 1;
            m &= m - 1u;
            unsigned off = chunkbase + rel;
            if (off < (unsigned)n) {
                unsigned idx = wi * 32u + (unsigned)bit;
                unsigned tt = idx >> 18;
                if (tt >= 128u) {                   // valid (non-wrapped) key
                    float* o3 = outP + 3ull * off;
                    o3[0] = (float)(tt - 128u);
                    o3[1] = (float)((idx >> 9) & 511u);
                    o3[2] = (float)(idx & 511u);
                }
            }
            rel++;
        }
    }
}

// P3b: cached query key -> presence check -> rank -> byte-mask atomicOr
__global__ void k_scatter(int n) {
    int i = blockIdx.x * blockDim.x + threadIdx.x;
    if (i >= n) return;
    unsigned k = g_key[i];
    unsigned idx = k >> 3, c = k & 7u;
    unsigned w = idx >> 5, b = idx & 31u;
    unsigned word = g_pbm[w];
    if (!((word >> b) & 1u)) return;              // aliased parent not in table
    unsigned r = g_chunkoff[w >> 10] + (unsigned)g_woff16[w]
               + (unsigned)__popc(word & ((1u << b) - 1u));
    if (r >= (unsigned)n) return;
    atomicOr(&g_cmask[r >> 2], (1u << c) << ((r & 3u) * 8u));
}

// P4: stream occupancy once, coalesced (unwritten ranks read zero masks)
__global__ void k_finalize(float* __restrict__ outO, int n) {
    int r = blockIdx.x * blockDim.x + threadIdx.x;
    if (r >= n) return;
    unsigned mask = (g_cmask[r >> 2] >> ((r & 3) * 8)) & 0xffu;
    float* o = outO + 8ull * r;
    if ((((uintptr_t)o) & 15u) == 0u) {
        ((float4*)o)[0] = make_float4((float)(mask & 1u), (float)((mask >> 1) & 1u),
                                      (float)((mask >> 2) & 1u), (float)((mask >> 3) & 1u));
        ((float4*)o)[1] = make_float4((float)((mask >> 4) & 1u), (float)((mask >> 5) & 1u),
                                      (float)((mask >> 6) & 1u), (float)((mask >> 7) & 1u));
    } else {
#pragma unroll
        for (int c = 0; c < 8; c++) o[c] = (float)((mask >> c) & 1u);
    }
}

extern "C" void kernel_launch(void* const* d_in, const int* in_sizes, int n_in,
                              void* d_out, int out_size) {
    (void)n_in;
    const float* leaf = (const float*)d_in[0];
    long long in0 = (long long)in_sizes[0];
    long long os = (long long)out_size;
    long long nll = (in0 % 3 == 0) ? in0 / 3 : ((os % 11 == 0) ? os / 11 : in0 / 3);
    if (nll > NMAX) nll = NMAX;
    int n = (int)nll;

    float* out = (float*)d_out;
    float* outP = out;
    float* outO = out + 3ll * n;

    const int TB = 256;
    int gb = (n + TB - 1) / TB;
    long long n3 = 3ll * n;
    int cmw = n / 4 + 2;
    long long fillq = (n3 + 3) / 4;
    long long fillt = fillq > (long long)(PB_WORDS / 4) ? fillq : (long long)(PB_WORDS / 4);

    k_fill<<<(unsigned)((fillt + TB - 1) / TB), TB>>>(outP, n3, cmw);
    k_mark<<<gb, TB>>>(leaf, n);
    k_scan<<<1, 1024>>>();
    k_emit<<<NCHUNKS, 256>>>(outP, n);
    k_scatter<<<gb, TB>>>(n);
    k_finalize<<<gb, TB>>>(outO, n);
}

// round 17
// speedup vs baseline: 2.0248x; 2.0248x over previous
#include <cuda_runtime.h>
#include <stdint.h>

// ---------------------------------------------------------------------------
// octree_level, int32-key-overflow semantics (verified rel=0 R13/R14/R16).
// R17 = R14 structure (best: 74.4us) with emit split into:
//   k_emit: rank offsets + g_idx[rank]=idx (4B scattered)
//   k_parent: coalesced rank-order stream -> outP rows (coords/-1)
// outP prefill removed. 7 launches.
// ---------------------------------------------------------------------------

#define PB_WORDS    (1u << 21)                 // 2^26 bits / 32  (8 MB)
#define CHUNK_WORDS 1024u
#define NCHUNKS     (PB_WORDS / CHUNK_WORDS)   // 2048
#define NMAX        2200000

__device__ __align__(16) unsigned g_pbm[PB_WORDS];
__device__ unsigned short g_woff16[PB_WORDS];  // chunk-relative rank of word
__device__ unsigned g_partial[NCHUNKS];
__device__ unsigned g_chunkoff[NCHUNKS];
__device__ unsigned g_M;
__device__ unsigned g_idx[NMAX];               // bit index per rank

// F: zero bitmap + occupancy region (outO background)
__global__ void k_fill(float* __restrict__ outO, long long n8q) {
    long long i = (long long)blockIdx.x * blockDim.x + threadIdx.x;
    if (i < PB_WORDS / 4) ((uint4*)g_pbm)[i] = make_uint4(0u, 0u, 0u, 0u);
    if (i < n8q) ((float4*)outO)[i] = make_float4(0.f, 0.f, 0.f, 0.f);
}

// K1: mark each leaf's own parent (wrapped key -> signed-order bit index)
__global__ void k_mark(const float* __restrict__ leaf, int n) {
    int i = blockIdx.x * blockDim.x + threadIdx.x;
    if (i >= n) return;
    int x = (int)leaf[3 * i + 0];
    int y = (int)leaf[3 * i + 1];
    int z = (int)leaf[3 * i + 2];
    x = min(max(x, 0), 1023); y = min(max(y, 0), 1023); z = min(max(z, 0), 1023);
    unsigned t = (((unsigned)(x >> 1)) & 255u) ^ 128u;    // pxm ^ 128
    unsigned idx = (t << 18) | ((unsigned)(y >> 1) << 9) | (unsigned)(z >> 1);
    atomicOr(&g_pbm[idx >> 5], 1u << (idx & 31u));
}

// P1: per-chunk popcount (256 thr x uint4 = 1024 words)
__global__ void k_count() {
    __shared__ unsigned sh[256];
    unsigned t = threadIdx.x;
    const uint4* base = ((const uint4*)g_pbm) + blockIdx.x * (CHUNK_WORDS / 4);
    uint4 w = base[t];
    unsigned s = __popc(w.x) + __popc(w.y) + __popc(w.z) + __popc(w.w);
    sh[t] = s; __syncthreads();
    for (int o = 128; o > 0; o >>= 1) {
        if (t < (unsigned)o) sh[t] += sh[t + o];
        __syncthreads();
    }
    if (t == 0) g_partial[blockIdx.x] = sh[0];
}

// P2: shuffle-based exclusive scan of 2048 chunk counts; total -> g_M
__global__ void k_scan() {
    __shared__ unsigned wsum[32];
    unsigned t = threadIdx.x, lane = t & 31u, wid = t >> 5;
    unsigned v0 = g_partial[2 * t + 0], v1 = g_partial[2 * t + 1];
    unsigned s = v0 + v1;
    unsigned x = s;
#pragma unroll
    for (int o = 1; o < 32; o <<= 1) {
        unsigned y = __shfl_up_sync(0xffffffffu, x, o);
        if (lane >= (unsigned)o) x += y;
    }
    if (lane == 31u) wsum[wid] = x;
    __syncthreads();
    if (wid == 0) {
        unsigned w = wsum[lane];
#pragma unroll
        for (int o = 1; o < 32; o <<= 1) {
            unsigned y = __shfl_up_sync(0xffffffffu, w, o);
            if (lane >= (unsigned)o) w += y;
        }
        wsum[lane] = w;
    }
    __syncthreads();
    unsigned base = ((wid > 0u) ? wsum[wid - 1] : 0u) + x - s;
    g_chunkoff[2 * t + 0] = base;
    g_chunkoff[2 * t + 1] = base + v0;
    if (t == 1023u) g_M = wsum[31];
}

// P3a: word offsets (u16) + g_idx[rank] = bit index (4B scattered)
__global__ void k_emit(int n) {
    __shared__ unsigned sh[256];
    unsigned b = blockIdx.x, t = threadIdx.x;
    unsigned w0 = b * CHUNK_WORDS + t * 4u;
    const uint4* base = ((const uint4*)g_pbm) + b * (CHUNK_WORDS / 4);
    uint4 w = base[t];
    unsigned words[4] = { w.x, w.y, w.z, w.w };
    unsigned s = __popc(w.x) + __popc(w.y) + __popc(w.z) + __popc(w.w);
    sh[t] = s; __syncthreads();
    for (int o = 1; o < 256; o <<= 1) {
        unsigned add = (t >= (unsigned)o) ? sh[t - o] : 0u;
        __syncthreads();
        sh[t] += add;
        __syncthreads();
    }
    unsigned rel = sh[t] - s;
    unsigned chunkbase = g_chunkoff[b];
#pragma unroll
    for (int j = 0; j < 4; j++) {
        unsigned wi = w0 + (unsigned)j;
        g_woff16[wi] = (unsigned short)rel;
        unsigned m = words[j];
        while (m) {
            int bit = __ffs((int)m) - 1;
            m &= m - 1u;
            unsigned off = chunkbase + rel;
            if (off < (unsigned)n) g_idx[off] = wi * 32u + (unsigned)bit;
            rel++;
        }
    }
}

// P3b: coalesced rank-order parent writer (coords / -1 wrapped / -1 tail)
__global__ void k_parent(float* __restrict__ outP, int n) {
    int r = blockIdx.x * blockDim.x + threadIdx.x;
    if (r >= n) return;
    unsigned M = g_M;
    float c0 = -1.0f, c1 = -1.0f, c2 = -1.0f;
    if ((unsigned)r < M) {
        unsigned idx = g_idx[r];
        unsigned tt = idx >> 18;
        if (tt >= 128u) {                           // valid (non-wrapped) key
            c0 = (float)(tt - 128u);
            c1 = (float)((idx >> 9) & 511u);
            c2 = (float)(idx & 511u);
        }
    }
    float* o3 = outP + 3ull * r;
    o3[0] = c0; o3[1] = c1; o3[2] = c2;
}

// P4: leaf lights occupancy slot of ALIASED parent directly (idempotent 1.0f)
__global__ void k_scatter(const float* __restrict__ leaf,
                          float* __restrict__ outO, int n) {
    int i = blockIdx.x * blockDim.x + threadIdx.x;
    if (i >= n) return;
    int x = (int)leaf[3 * i + 0];
    int y = (int)leaf[3 * i + 1];
    int z = (int)leaf[3 * i + 2];
    x = min(max(x, 0), 1023); y = min(max(y, 0), 1023); z = min(max(z, 0), 1023);
    unsigned pxm = ((unsigned)x & 255u) >> 1;             // aliased parent x
    unsigned t2 = pxm + 128u;                             // valid zone (^128)
    unsigned idx = (t2 << 18) | ((unsigned)(y >> 1) << 9) | (unsigned)(z >> 1);
    unsigned w = idx >> 5, b = idx & 31u;
    unsigned word = g_pbm[w];
    if (!((word >> b) & 1u)) return;                      // parent absent
    unsigned r = g_chunkoff[w >> 10] + (unsigned)g_woff16[w]
               + (unsigned)__popc(word & ((1u << b) - 1u));
    if (r >= (unsigned)n) return;
    unsigned c = ((unsigned)(x & 1) << 2) | ((unsigned)(y & 1) << 1) | (unsigned)(z & 1);
    outO[8ull * r + c] = 1.0f;
}

extern "C" void kernel_launch(void* const* d_in, const int* in_sizes, int n_in,
                              void* d_out, int out_size) {
    (void)n_in;
    const float* leaf = (const float*)d_in[0];
    long long in0 = (long long)in_sizes[0];
    long long os = (long long)out_size;
    long long nll = (in0 % 3 == 0) ? in0 / 3 : ((os % 11 == 0) ? os / 11 : in0 / 3);
    if (nll > NMAX) nll = NMAX;
    int n = (int)nll;

    float* out = (float*)d_out;
    float* outP = out;              // [0,3n): parent rows
    float* outO = out + 3ll * n;    // [3n,11n): occupancy

    const int TB = 256;
    int gb = (n + TB - 1) / TB;
    long long n8q = (8ll * n) / 4;  // float4 count for occupancy zero (8n % 4 == 0)
    long long fillt = n8q > (long long)(PB_WORDS / 4) ? n8q : (long long)(PB_WORDS / 4);

    k_fill<<<(unsigned)((fillt + TB - 1) / TB), TB>>>(outO, n8q);
    k_mark<<<gb, TB>>>(leaf, n);
    k_count<<<NCHUNKS, 256>>>();
    k_scan<<<1, 1024>>>();
    k_emit<<<NCHUNKS, 256>>>(n);
    k_parent<<<gb, TB>>>(outP, n);
    k_scatter<<<gb, TB>>>(leaf, outO, n);
}